// round 2
// baseline (speedup 1.0000x reference)
#include <cuda_runtime.h>
#include <stdint.h>

#define NUSERS 50000
#define NITEMS 30000
#define NNODES 80000
#define EK 64
#define HH 32
#define NNZADJ 2000000
#define NNZR 1000000

// ---------------- scratch (device globals; allocation is forbidden) ----------------
__device__ float g_itemfeat[NITEMS * EK];
__device__ float g_ihl[NITEMS * HH];
__device__ float g_uhl[NUSERS * HH];
__device__ float g_ih[2 * NITEMS * HH];
__device__ float g_uh[2 * NUSERS * HH];
__device__ float g_e0[NNODES * EK];
__device__ float g_e1[NNODES * EK];
__device__ float g_e2[NNODES * EK];
__device__ float g_m0[NNODES * EK];
__device__ float g_m1[NNODES * EK];
__device__ float g_msum[NNODES * EK];
__device__ float g_lat[HH * EK];

// ---------------- threefry2x32 (JAX-compatible, 20 rounds) ----------------
__host__ __device__ __forceinline__ void tf2x32(uint32_t k0, uint32_t k1,
                                                uint32_t x0, uint32_t x1,
                                                uint32_t* o0, uint32_t* o1) {
  uint32_t ks2 = k0 ^ k1 ^ 0x1BD11BDAu;
  uint32_t v0 = x0 + k0, v1 = x1 + k1;
#define TFR(r) { v0 += v1; v1 = (v1 << (r)) | (v1 >> (32 - (r))); v1 ^= v0; }
  TFR(13) TFR(15) TFR(26) TFR(6)
  v0 += k1;  v1 += ks2 + 1u;
  TFR(17) TFR(29) TFR(16) TFR(24)
  v0 += ks2; v1 += k0 + 2u;
  TFR(13) TFR(15) TFR(26) TFR(6)
  v0 += k0;  v1 += k1 + 3u;
  TFR(17) TFR(29) TFR(16) TFR(24)
  v0 += k1;  v1 += ks2 + 4u;
  TFR(13) TFR(15) TFR(26) TFR(6)
  v0 += ks2; v1 += k0 + 5u;
#undef TFR
  *o0 = v0; *o1 = v1;
}

// ---------------- vector atomic add ----------------
__device__ __forceinline__ void red_add_f4(float4* p, float4 v) {
  asm volatile("red.global.add.v4.f32 [%0], {%1,%2,%3,%4};"
               :: "l"(p), "f"(v.x), "f"(v.y), "f"(v.z), "f"(v.w) : "memory");
}

// ---------------- SpMM scatter: y[rows[e]] += vals[e] * x[cols[e]] (y pre-zeroed) ----------------
template <int C4>
__global__ void spmm_kernel(const int* __restrict__ rows, const int* __restrict__ cols,
                            const float* __restrict__ vals, const float4* __restrict__ x,
                            float4* __restrict__ y, int nnz) {
  int idx = blockIdx.x * 256 + threadIdx.x;
  if (idx >= nnz * C4) return;
  int e = idx / C4;
  int c = idx - e * C4;
  int r = rows[e];
  int cl = cols[e];
  float v = vals[e];
  float4 xv = __ldg(x + cl * C4 + c);
  float4 pr = make_float4(v * xv.x, v * xv.y, v * xv.z, v * xv.w);
  red_add_f4(y + r * C4 + c, pr);
}

// ---------------- fused GEMM: Cf[NITEMS,64] = A@Bt, Cl[NITEMS,32] = A@Bh ----------------
__global__ __launch_bounds__(256, 2)
void gemm_fused_kernel(const float* __restrict__ A, const float* __restrict__ Bt,
                       const float* __restrict__ Bh, float* __restrict__ Cf,
                       float* __restrict__ Cl, int F) {
  __shared__ float As[32][129];
  __shared__ float Bs[32][97];
  const int row0 = blockIdx.x * 128;
  const int tx = threadIdx.x & 15;   // col group (6 cols)
  const int ty = threadIdx.x >> 4;   // row group (8 rows)
  float acc[8][6];
#pragma unroll
  for (int i = 0; i < 8; i++)
#pragma unroll
    for (int j = 0; j < 6; j++) acc[i][j] = 0.0f;

  for (int k0 = 0; k0 < F; k0 += 32) {
    for (int t = threadIdx.x; t < 128 * 32; t += 256) {
      int r = t >> 5, kk = t & 31;
      int gr = row0 + r;
      As[kk][r] = (gr < NITEMS) ? A[(size_t)gr * F + k0 + kk] : 0.0f;
    }
    for (int t = threadIdx.x; t < 32 * 96; t += 256) {
      int kk = t / 96, c = t - kk * 96;
      Bs[kk][c] = (c < 64) ? Bt[(k0 + kk) * 64 + c] : Bh[(k0 + kk) * 32 + (c - 64)];
    }
    __syncthreads();
#pragma unroll 8
    for (int kk = 0; kk < 32; kk++) {
      float a[8], b[6];
#pragma unroll
      for (int i = 0; i < 8; i++) a[i] = As[kk][ty * 8 + i];
#pragma unroll
      for (int j = 0; j < 6; j++) b[j] = Bs[kk][tx * 6 + j];
#pragma unroll
      for (int i = 0; i < 8; i++)
#pragma unroll
        for (int j = 0; j < 6; j++) acc[i][j] = fmaf(a[i], b[j], acc[i][j]);
    }
    __syncthreads();
  }
#pragma unroll
  for (int i = 0; i < 8; i++) {
    int gr = row0 + ty * 8 + i;
    if (gr < NITEMS) {
#pragma unroll
      for (int j = 0; j < 6; j++) {
        int c = tx * 6 + j;
        if (c < 64) Cf[gr * 64 + c] = acc[i][j];
        else        Cl[gr * 32 + (c - 64)] = acc[i][j];
      }
    }
  }
}

// ---------------- gumbel softmax (JAX partitionable threefry), warp per row ----------------
__global__ void gumbel_kernel(const float* __restrict__ logits, float* __restrict__ out,
                              int rows, unsigned k0, unsigned k1) {
  int row = blockIdx.x * 8 + (threadIdx.x >> 5);
  if (row >= rows) return;
  int lane = threadIdx.x & 31;
  unsigned idx = (unsigned)row * 32u + (unsigned)lane;
  unsigned o0, o1;
  tf2x32(k0, k1, 0u, idx, &o0, &o1);
  unsigned bits = o0 ^ o1;
  float f = __uint_as_float((bits >> 9) | 0x3f800000u) - 1.0f;
  const float TINY = 1.1754943508222875e-38f;
  float u = fmaxf(TINY, f + TINY);
  float g = -logf(-logf(u));
  float z = (logits[row * 32 + lane] + g) * 5.0f;  // /tau, tau=0.2
  float mx = z;
#pragma unroll
  for (int s = 16; s; s >>= 1) mx = fmaxf(mx, __shfl_xor_sync(0xffffffffu, mx, s));
  float e = expf(z - mx);
  float sm = e;
#pragma unroll
  for (int s = 16; s; s >>= 1) sm += __shfl_xor_sync(0xffffffffu, sm, s);
  out[row * 32 + lane] = e / sm;
}

// ---------------- small elementwise ----------------
__global__ void concat_kernel(const float* __restrict__ Gu, const float* __restrict__ Gi,
                              float* __restrict__ e0) {
  int idx = blockIdx.x * 256 + threadIdx.x;
  if (idx >= NNODES * EK) return;
  e0[idx] = (idx < NUSERS * EK) ? Gu[idx] : Gi[idx - NUSERS * EK];
}

__global__ void cge_combine_kernel(float* __restrict__ e0, const float* __restrict__ e1,
                                   const float* __restrict__ e2) {
  int idx = blockIdx.x * 256 + threadIdx.x;
  if (idx >= NNODES * EK) return;
  e0[idx] = (e0[idx] + e1[idx] + e2[idx]) * (1.0f / 3.0f);
}

__global__ void scale_copy_kernel(float* __restrict__ m0, const float* __restrict__ itf,
                                  const float* __restrict__ inv) {
  int idx = blockIdx.x * 256 + threadIdx.x;
  if (idx >= NNODES * EK) return;
  int row = idx >> 6;
  if (row < NUSERS) m0[idx] *= inv[row];
  else              m0[idx] = itf[idx - NUSERS * EK];
}

// acc[row] += x[row]/max(||x[row]||,1e-12); warp per row (64 cols)
__global__ void l2norm_add_kernel(const float* __restrict__ x, float* __restrict__ acc) {
  int row = blockIdx.x * 8 + (threadIdx.x >> 5);
  if (row >= NNODES) return;
  int lane = threadIdx.x & 31;
  int b = row * EK;
  float a0 = x[b + lane], a1 = x[b + lane + 32];
  float ss = a0 * a0 + a1 * a1;
#pragma unroll
  for (int s = 16; s; s >>= 1) ss += __shfl_xor_sync(0xffffffffu, ss, s);
  float inv = 1.0f / fmaxf(sqrtf(ss), 1e-12f);
  acc[b + lane]      += a0 * inv;
  acc[b + lane + 32] += a1 * inv;
}

// ---------------- lat[32,64] += ih^T @ icge over item chunk (lat pre-zeroed) ----------------
__global__ void lat_kernel(const float* __restrict__ w, const float* __restrict__ icge,
                           float* __restrict__ lat, int chunk) {
  int lane = threadIdx.x & 31;
  int kg = threadIdx.x >> 5;  // 0..7
  int start = blockIdx.x * chunk;
  int end = min(start + chunk, NITEMS);
  float acc[8] = {0, 0, 0, 0, 0, 0, 0, 0};
  for (int it = start; it < end; ++it) {
    float wv = w[it * HH + lane];
    const float* cr = icge + it * EK + kg * 8;
#pragma unroll
    for (int j = 0; j < 8; j++) acc[j] = fmaf(wv, __ldg(cr + j), acc[j]);
  }
#pragma unroll
  for (int j = 0; j < 8; j++) atomicAdd(&lat[lane * EK + kg * 8 + j], acc[j]);
}

// ---------------- out[rows,64] = w[rows,32] @ lat[32,64] ----------------
__global__ void hyper_apply_kernel(const float* __restrict__ w, const float* __restrict__ lat,
                                   float* __restrict__ out, int rows) {
  __shared__ float sl[HH * EK];
  for (int t = threadIdx.x; t < HH * EK; t += 256) sl[t] = lat[t];
  __syncthreads();
  int idx = blockIdx.x * 256 + threadIdx.x;
  if (idx >= rows * EK) return;
  int r = idx >> 6, k = idx & 63;
  float s = 0.0f;
#pragma unroll
  for (int h = 0; h < HH; h++) s = fmaf(w[r * HH + h], sl[h * EK + k], s);
  out[idx] = s;
}

// ---------------- final: all_embs = cge + msum + 0.2*l2norm(ghe), ghe read from d_out ----------------
__global__ void final_kernel(float* __restrict__ out, const float* __restrict__ cge,
                             const float* __restrict__ msum) {
  const int OI   = NUSERS * EK;
  const int OHVU = (NUSERS + NITEMS) * EK;
  const int OHVI = OHVU + NUSERS * EK;
  const int OHTU = OHVI + NITEMS * EK;
  const int OHTI = OHTU + NUSERS * EK;
  int row = blockIdx.x * 8 + (threadIdx.x >> 5);
  if (row >= NNODES) return;
  int lane = threadIdx.x & 31;
  const float* hv;
  const float* ht;
  float* dst;
  if (row < NUSERS) {
    hv = out + OHVU + row * EK; ht = out + OHTU + row * EK; dst = out + row * EK;
  } else {
    int ir = row - NUSERS;
    hv = out + OHVI + ir * EK;  ht = out + OHTI + ir * EK;  dst = out + OI + ir * EK;
  }
  float g0 = hv[lane] + ht[lane];
  float g1 = hv[lane + 32] + ht[lane + 32];
  float ss = g0 * g0 + g1 * g1;
#pragma unroll
  for (int s = 16; s; s >>= 1) ss += __shfl_xor_sync(0xffffffffu, ss, s);
  float inv = 0.2f / fmaxf(sqrtf(ss), 1e-12f);
  int b = row * EK;
  dst[lane]      = cge[b + lane]      + msum[b + lane]      + g0 * inv;
  dst[lane + 32] = cge[b + lane + 32] + msum[b + lane + 32] + g1 * inv;
}

// ================================================================================
extern "C" void kernel_launch(void* const* d_in, const int* in_sizes, int n_in,
                              void* d_out, int out_size) {
  const float* Gu       = (const float*)d_in[0];
  const float* Gi       = (const float*)d_in[1];
  const float* feat_v   = (const float*)d_in[2];
  const float* feat_t   = (const float*)d_in[3];
  const float* trs_v    = (const float*)d_in[4];
  const float* trs_t    = (const float*)d_in[5];
  const float* hyp_v    = (const float*)d_in[6];
  const float* hyp_t    = (const float*)d_in[7];
  const float* inv      = (const float*)d_in[8];
  const float* adj_vals = (const float*)d_in[9];
  const float* r_vals   = (const float*)d_in[10];
  const int*   adj_rows = (const int*)d_in[11];
  const int*   adj_cols = (const int*)d_in[12];
  const int*   r_rows   = (const int*)d_in[13];
  const int*   r_cols   = (const int*)d_in[14];
  float* out = (float*)d_out;
  int Fv = in_sizes[2] / NITEMS;
  int Ft = in_sizes[3] / NITEMS;

  float *p_itf, *p_ihl, *p_uhl, *p_ih, *p_uh, *p_e0, *p_e1, *p_e2, *p_m0, *p_m1, *p_msum, *p_lat;
  cudaGetSymbolAddress((void**)&p_itf,  g_itemfeat);
  cudaGetSymbolAddress((void**)&p_ihl,  g_ihl);
  cudaGetSymbolAddress((void**)&p_uhl,  g_uhl);
  cudaGetSymbolAddress((void**)&p_ih,   g_ih);
  cudaGetSymbolAddress((void**)&p_uh,   g_uh);
  cudaGetSymbolAddress((void**)&p_e0,   g_e0);
  cudaGetSymbolAddress((void**)&p_e1,   g_e1);
  cudaGetSymbolAddress((void**)&p_e2,   g_e2);
  cudaGetSymbolAddress((void**)&p_m0,   g_m0);
  cudaGetSymbolAddress((void**)&p_m1,   g_m1);
  cudaGetSymbolAddress((void**)&p_msum, g_msum);
  cudaGetSymbolAddress((void**)&p_lat,  g_lat);

  // JAX threefry keys (host arithmetic; deterministic)
  uint32_t ki0[2], ki1[2], ku0[2], ku1[2];
  for (int m = 0; m < 2; m++) {
    uint32_t km0, km1;
    tf2x32(0u, 42u, 0u, (uint32_t)m, &km0, &km1);       // fold_in(key(42), m)
    tf2x32(km0, km1, 0u, 0u, &ki0[m], &ki1[m]);         // split -> k1 (i_hyper)
    tf2x32(km0, km1, 0u, 1u, &ku0[m], &ku1[m]);         // split -> k2 (u_hyper)
  }

  const size_t NB = (size_t)NNODES * EK * sizeof(float);
  const int GN = (NNODES * EK + 255) / 256;

  // ---- cge path ----
  concat_kernel<<<GN, 256>>>(Gu, Gi, p_e0);
  cudaMemsetAsync(p_e1, 0, NB, 0);
  spmm_kernel<16><<<(NNZADJ * 16 + 255) / 256, 256>>>(adj_rows, adj_cols, adj_vals,
                                                      (const float4*)p_e0, (float4*)p_e1, NNZADJ);
  cudaMemsetAsync(p_e2, 0, NB, 0);
  spmm_kernel<16><<<(NNZADJ * 16 + 255) / 256, 256>>>(adj_rows, adj_cols, adj_vals,
                                                      (const float4*)p_e1, (float4*)p_e2, NNZADJ);
  cge_combine_kernel<<<GN, 256>>>(p_e0, p_e1, p_e2);   // p_e0 = cge
  cudaMemsetAsync(p_msum, 0, NB, 0);

  // ---- per-modality: gemm, gumbel, mge ----
  for (int m = 0; m < 2; m++) {
    const float* feat = m ? feat_t : feat_v;
    const float* trs  = m ? trs_t  : trs_v;
    const float* hyp  = m ? hyp_t  : hyp_v;
    int F = m ? Ft : Fv;
    gemm_fused_kernel<<<(NITEMS + 127) / 128, 256>>>(feat, trs, hyp, p_itf, p_ihl, F);
    gumbel_kernel<<<(NITEMS + 7) / 8, 256>>>(p_ihl, p_ih + m * NITEMS * HH, NITEMS, ki0[m], ki1[m]);
    cudaMemsetAsync(p_uhl, 0, (size_t)NUSERS * HH * sizeof(float), 0);
    spmm_kernel<8><<<(NNZR * 8 + 255) / 256, 256>>>(r_rows, r_cols, r_vals,
                                                    (const float4*)p_ihl, (float4*)p_uhl, NNZR);
    gumbel_kernel<<<(NUSERS + 7) / 8, 256>>>(p_uhl, p_uh + m * NUSERS * HH, NUSERS, ku0[m], ku1[m]);

    cudaMemsetAsync(p_m0, 0, NB, 0);
    spmm_kernel<16><<<(NNZR * 16 + 255) / 256, 256>>>(r_rows, r_cols, r_vals,
                                                      (const float4*)p_itf, (float4*)p_m0, NNZR);
    scale_copy_kernel<<<GN, 256>>>(p_m0, p_itf, inv);
    cudaMemsetAsync(p_m1, 0, NB, 0);
    spmm_kernel<16><<<(NNZADJ * 16 + 255) / 256, 256>>>(adj_rows, adj_cols, adj_vals,
                                                        (const float4*)p_m0, (float4*)p_m1, NNZADJ);
    l2norm_add_kernel<<<(NNODES + 7) / 8, 256>>>(p_m1, p_msum);
  }

  // ---- hyper path (writes u_ret/i_ret straight into d_out) ----
  const int OHVU = (NUSERS + NITEMS) * EK;
  const int OHVI = OHVU + NUSERS * EK;
  const int OHTU = OHVI + NITEMS * EK;
  const int OHTI = OHTU + NUSERS * EK;
  for (int m = 0; m < 2; m++) {
    cudaMemsetAsync(p_lat, 0, HH * EK * sizeof(float), 0);
    lat_kernel<<<120, 256>>>(p_ih + m * NITEMS * HH, p_e0 + NUSERS * EK, p_lat, (NITEMS + 119) / 120);
    hyper_apply_kernel<<<(NITEMS * EK + 255) / 256, 256>>>(
        p_ih + m * NITEMS * HH, p_lat, out + (m ? OHTI : OHVI), NITEMS);
    hyper_apply_kernel<<<(NUSERS * EK + 255) / 256, 256>>>(
        p_uh + m * NUSERS * HH, p_lat, out + (m ? OHTU : OHVU), NUSERS);
  }

  final_kernel<<<(NNODES + 7) / 8, 256>>>(out, p_e0, p_msum);
}